// round 11
// baseline (speedup 1.0000x reference)
#include <cuda_runtime.h>
#include <math.h>
#include <stdint.h>

#define B_ 64
#define C_ 3
#define N_ 512
#define TILE_Y 8
#define TILE_X 256
#define HALO_R (TILE_Y + 2)                // 10 rows incl. halo
#define TW     260                         // loaded cols per tile (16B aligned)
#define CH_F   (HALO_R * TW)               // floats per channel tile (2600)
#define SMEM_BYTES (C_ * CH_F * 4)         // 31200

__device__ __forceinline__ uint32_t smem_u32(const void* p) {
    uint32_t a;
    asm("{ .reg .u64 t; cvta.to.shared.u64 t, %1; cvt.u32.u64 %0, t; }"
        : "=r"(a) : "l"(p));
    return a;
}

__global__ void __launch_bounds__(256)
diffeo_kernel(const float* __restrict__ x,
              const float* __restrict__ Fx,
              const float* __restrict__ Fy,
              float* __restrict__ out,
              float scale) {
    extern __shared__ float S[];                       // [3][HALO_R][TW]
    __shared__ __align__(8) unsigned long long mbar;

    // envelope e[i][j] = 1/sqrt((i+1)^2+(j+1)^2), zeroed where r >= 4.5
    // constexpr -> folds to immediates under full unroll
    constexpr float ENV[16] = {
        0.7071067812f, 0.4472135955f, 0.3162277660f, 0.2425356250f,
        0.4472135955f, 0.3535533906f, 0.2773500981f, 0.2236067977f,
        0.3162277660f, 0.2773500981f, 0.2357022604f, 0.0f,
        0.2425356250f, 0.2236067977f, 0.0f,          0.0f
    };

    const int tid  = threadIdx.x;
    const int b    = blockIdx.z;
    const int y0   = blockIdx.y * TILE_Y;
    const int x0   = blockIdx.x * TILE_X;
    const int warp = tid >> 5;
    const int lane = tid & 31;
    const int y    = y0 + warp;                        // one warp per output row

    const int gx0  = (x0 == 0) ? 0 : (x0 - 4);         // loaded col window start

    // row window
    int gy0 = y0 - 1, lr0 = 0;
    if (gy0 < 0) { gy0 = 0; lr0 = 1; }
    int gy1 = y0 + TILE_Y;
    if (gy1 > N_ - 1) gy1 = N_ - 1;
    const int nrows = gy1 - gy0 + 1;                   // 9 or 10

    const uint32_t mb = smem_u32(&mbar);

    if (tid == 0) {
        asm volatile("mbarrier.init.shared.b64 [%0], %1;" :: "r"(mb), "r"(1u) : "memory");
        const unsigned total = (unsigned)(C_ * nrows) * (TW * 4u);
        asm volatile("mbarrier.arrive.expect_tx.shared.b64 _, [%0], %1;"
                     :: "r"(mb), "r"(total) : "memory");
    }
    __syncthreads();

    // 3*nrows parallel 1040B bulk copies (one per channel-row)
    if (tid < C_ * nrows) {
        const int c = tid / nrows;
        const int r = tid - c * nrows;
        const float* src = x + ((size_t)(b * C_ + c) * N_ + (gy0 + r)) * N_ + gx0;
        const uint32_t dst = smem_u32(S + c * CH_F + (lr0 + r) * TW);
        asm volatile(
            "cp.async.bulk.shared::cta.global.mbarrier::complete_tx::bytes "
            "[%0], [%1], %2, [%3];"
            :: "r"(dst), "l"(src), "r"((unsigned)(TW * 4)), "r"(mb) : "memory");
    }

    // ---- per-warp row coefficients (overlaps the bulk copies) ----
    const float PI_INV = (float)M_PI / (float)(N_ - 1);
    const float py = (float)y * PI_INV;
    const float sy0 = __sinf(py), sy1 = __sinf(py * 2.0f);
    const float sy2 = __sinf(py * 3.0f), sy3 = __sinf(py * 4.0f);

    float gu[4], gv[4];
#pragma unroll
    for (int i = 0; i < 4; i++) {
        float4 fx  = __ldg((const float4*)(Fx + b * 16 + i * 4));
        float4 fy4 = __ldg((const float4*)(Fy + b * 16 + i * 4));
        gu[i] = fmaf(fx.x * ENV[i*4+0], sy0, fmaf(fx.y * ENV[i*4+1], sy1,
                fmaf(fx.z * ENV[i*4+2], sy2,      fx.w * ENV[i*4+3] * sy3)));
        gv[i] = fmaf(fy4.x * ENV[i*4+0], sy0, fmaf(fy4.y * ENV[i*4+1], sy1,
                fmaf(fy4.z * ENV[i*4+2], sy2,     fy4.w * ENV[i*4+3] * sy3)));
    }

    float s1 = __sinf((float)(x0 + lane) * PI_INV);
    float c1 = __cosf((float)(x0 + lane) * PI_INV);
    const float stepA = 32.0f * PI_INV;
    const float sd = __sinf(stepA), cd = __cosf(stepA);

    const float fy = (float)y;
    const float HIG = __uint_as_float(0x43FF7FFFu);    // 510.99997
    // window clamps: inactive unless |displacement| >= 1 (impossible, ~8 sigma)
    const float LOX = (x0 > 0) ? (float)(x0 - 1) : 0.0f;
    const float HIXt = fminf(HIG, (float)(x0 + TILE_X) - 0.001f);
    const float LOY = (y0 > 0) ? (float)(y0 - 1) : 0.0f;
    const float HIY = fminf(HIG, (float)(y0 + TILE_Y) - 0.001f);
    const float ybase = (float)(y0 - 1);

    // ---- wait for the tile (acquire orders subsequent ld.shared) ----
    {
        uint32_t done;
        asm volatile(
            "{\n .reg .pred p;\n"
            " mbarrier.try_wait.parity.acquire.cta.shared::cta.b64 p, [%1], %2;\n"
            " selp.b32 %0, 1, 0, p;\n}"
            : "=r"(done) : "r"(mb), "r"(0u) : "memory");
        while (!done) {
            asm volatile(
                "{\n .reg .pred p;\n"
                " mbarrier.try_wait.parity.acquire.cta.shared::cta.b64 p, [%1], %2, 0x989680;\n"
                " selp.b32 %0, 1, 0, p;\n}"
                : "=r"(done) : "r"(mb), "r"(0u) : "memory");
        }
    }

    float* orow = out + (size_t)(b * C_) * (N_ * N_) + y * N_;

#pragma unroll 4
    for (int it = 0; it < TILE_X / 32; it++) {
        const int xi = x0 + it * 32 + lane;

        const float s2 = 2.0f * s1 * c1;
        const float c2 = fmaf(2.0f * c1, c1, -1.0f);
        const float s3 = fmaf(s1, c2, c1 * s2);
        const float s4 = 2.0f * s2 * c2;

        const float u = fmaf(gu[0], s1, fmaf(gu[1], s2, fmaf(gu[2], s3, gu[3] * s4)));
        const float v = fmaf(gv[0], s1, fmaf(gv[1], s2, fmaf(gv[2], s3, gv[3] * s4)));

        const float xn = fminf(fmaxf((float)xi - scale * u, LOX), HIXt);
        const float yn = fminf(fmaxf(fy        - scale * v, LOY), HIY);

        const float xff = floorf(xn);
        const float yff = floorf(yn);
        const int   lc  = (int)xff - gx0;              // local col
        const float xv  = xn - xff;
        const float yv  = yn - yff;
        const int   r   = (int)(yff - ybase);          // local halo row 0..9

        const float w00 = (1.0f - yv) * (1.0f - xv);
        const float w01 = (1.0f - yv) * xv;
        const float w10 = yv * (1.0f - xv);
        const float w11 = yv * xv;

        const float* base = S + r * TW + lc;           // taps: imm offsets

        float t[12];
#pragma unroll
        for (int c = 0; c < C_; c++) {
            const int off = c * CH_F;
            t[c*4+0] = base[off];
            t[c*4+1] = base[off + 1];
            t[c*4+2] = base[off + TW];
            t[c*4+3] = base[off + TW + 1];
        }

        const float ns = fmaf(s1, cd,  c1 * sd);
        const float nc = fmaf(c1, cd, -s1 * sd);
        s1 = ns; c1 = nc;

#pragma unroll
        for (int c = 0; c < C_; c++) {
            float val = fmaf(w00, t[c*4+0], fmaf(w01, t[c*4+1],
                        fmaf(w10, t[c*4+2],      w11 * t[c*4+3])));
            __stcs(&orow[c * (N_ * N_) + xi], val);
        }
    }
}

extern "C" void kernel_launch(void* const* d_in, const int* in_sizes, int n_in,
                              void* d_out, int out_size) {
    const float* x  = (const float*)d_in[0];
    const float* Fx = (const float*)d_in[1];
    const float* Fy = (const float*)d_in[2];
    float* out = (float*)d_out;

    const double n_d  = (double)N_;
    const double typ  = n_d * sqrt(M_PI * log(4.0)) / 2.0;
    const double T    = 0.01;
    const float scale = (float)(sqrt(T / (typ * typ)) * n_d);

    cudaFuncSetAttribute(diffeo_kernel,
                         cudaFuncAttributeMaxDynamicSharedMemorySize, SMEM_BYTES);

    dim3 block(256);
    dim3 grid(N_ / TILE_X, N_ / TILE_Y, B_);
    diffeo_kernel<<<grid, block, SMEM_BYTES>>>(x, Fx, Fy, out, scale);
}

// round 12
// speedup vs baseline: 1.0913x; 1.0913x over previous
#include <cuda_runtime.h>
#include <math.h>
#include <stdint.h>

#define B_ 64
#define C_ 3
#define N_ 512
#define TILE_Y 16
#define HALO_R (TILE_Y + 2)                 // 18 rows incl. halo
#define CH_F (HALO_R * N_)                  // floats per channel tile (9216)
#define SMEM_BYTES (C_ * CH_F * 4)          // 110592
#define SPLIT_L 11                          // rows [.,10] -> barrier A, [11,.] -> B

__device__ __forceinline__ uint32_t smem_u32(const void* p) {
    uint32_t a;
    asm("{ .reg .u64 t; cvta.to.shared.u64 t, %1; cvt.u32.u64 %0, t; }"
        : "=r"(a) : "l"(p));
    return a;
}

__device__ __forceinline__ void mbar_wait(uint32_t mb) {
    uint32_t done;
    asm volatile(
        "{\n .reg .pred p;\n"
        " mbarrier.try_wait.parity.acquire.cta.shared::cta.b64 p, [%1], %2;\n"
        " selp.b32 %0, 1, 0, p;\n}"
        : "=r"(done) : "r"(mb), "r"(0u) : "memory");
    while (!done) {
        asm volatile(
            "{\n .reg .pred p;\n"
            " mbarrier.try_wait.parity.acquire.cta.shared::cta.b64 p, [%1], %2, 0x989680;\n"
            " selp.b32 %0, 1, 0, p;\n}"
            : "=r"(done) : "r"(mb), "r"(0u) : "memory");
    }
}

__global__ void __launch_bounds__(512)
diffeo_kernel(const float* __restrict__ x,
              const float* __restrict__ Fx,
              const float* __restrict__ Fy,
              float* __restrict__ out,
              float scale) {
    extern __shared__ float S[];                        // [3][HALO_R][512]
    __shared__ __align__(8) unsigned long long mbarA, mbarB;

    // envelope e[i][j] = 1/sqrt((i+1)^2+(j+1)^2), zeroed where r >= 4.5
    constexpr float ENV[16] = {
        0.7071067812f, 0.4472135955f, 0.3162277660f, 0.2425356250f,
        0.4472135955f, 0.3535533906f, 0.2773500981f, 0.2236067977f,
        0.3162277660f, 0.2773500981f, 0.2357022604f, 0.0f,
        0.2425356250f, 0.2236067977f, 0.0f,          0.0f
    };

    const int tid  = threadIdx.x;
    const int b    = blockIdx.y;
    const int y0   = blockIdx.x * TILE_Y;
    const int warp = tid >> 5;
    const int lane = tid & 31;
    const int y    = y0 + warp;                         // one warp per output row

    // local row L <-> global row (y0-1+L); valid L in [Lmin, Lmax]
    const int Lmin = (y0 == 0) ? 1 : 0;
    const int Lmax = (y0 + TILE_Y > N_ - 1) ? (HALO_R - 2) : (HALO_R - 1);
    const int nA   = SPLIT_L - Lmin;                    // rows in group A
    const int nB   = Lmax - SPLIT_L + 1;                // rows in group B

    const uint32_t mbA = smem_u32(&mbarA);
    const uint32_t mbB = smem_u32(&mbarB);

    if (tid == 0) {
        asm volatile("mbarrier.init.shared.b64 [%0], %1;" :: "r"(mbA), "r"(1u) : "memory");
        asm volatile("mbarrier.init.shared.b64 [%0], %1;" :: "r"(mbB), "r"(1u) : "memory");
    }
    __syncthreads();

    if (tid == 0) {
        const unsigned bytesA = (unsigned)(C_ * nA) * (N_ * 4u);
        const unsigned bytesB = (unsigned)(C_ * nB) * (N_ * 4u);
        asm volatile("mbarrier.arrive.expect_tx.shared.b64 _, [%0], %1;"
                     :: "r"(mbA), "r"(bytesA) : "memory");
        asm volatile("mbarrier.arrive.expect_tx.shared.b64 _, [%0], %1;"
                     :: "r"(mbB), "r"(bytesB) : "memory");
#pragma unroll
        for (int c = 0; c < C_; c++) {
            // group A: local rows [Lmin, SPLIT_L-1]  (contiguous in gmem)
            const float* srcA = x + ((size_t)(b * C_ + c) * N_ + (y0 - 1 + Lmin)) * N_;
            const uint32_t dstA = smem_u32(S + c * CH_F + Lmin * N_);
            asm volatile(
                "cp.async.bulk.shared::cta.global.mbarrier::complete_tx::bytes "
                "[%0], [%1], %2, [%3];"
                :: "r"(dstA), "l"(srcA), "r"((unsigned)(nA * N_ * 4)), "r"(mbA) : "memory");
            // group B: local rows [SPLIT_L, Lmax]
            const float* srcB = x + ((size_t)(b * C_ + c) * N_ + (y0 - 1 + SPLIT_L)) * N_;
            const uint32_t dstB = smem_u32(S + c * CH_F + SPLIT_L * N_);
            asm volatile(
                "cp.async.bulk.shared::cta.global.mbarrier::complete_tx::bytes "
                "[%0], [%1], %2, [%3];"
                :: "r"(dstB), "l"(srcB), "r"((unsigned)(nB * N_ * 4)), "r"(mbB) : "memory");
        }
    }

    // ---- per-warp row coefficients (overlaps the bulk copies) ----
    const float PI_INV = (float)M_PI / (float)(N_ - 1);
    const float py = (float)y * PI_INV;
    const float sy0 = __sinf(py), sy1 = __sinf(py * 2.0f);
    const float sy2 = __sinf(py * 3.0f), sy3 = __sinf(py * 4.0f);

    float gu[4], gv[4];
#pragma unroll
    for (int i = 0; i < 4; i++) {
        float4 fx  = __ldg((const float4*)(Fx + b * 16 + i * 4));
        float4 fy4 = __ldg((const float4*)(Fy + b * 16 + i * 4));
        gu[i] = fmaf(fx.x * ENV[i*4+0], sy0, fmaf(fx.y * ENV[i*4+1], sy1,
                fmaf(fx.z * ENV[i*4+2], sy2,      fx.w * ENV[i*4+3] * sy3)));
        gv[i] = fmaf(fy4.x * ENV[i*4+0], sy0, fmaf(fy4.y * ENV[i*4+1], sy1,
                fmaf(fy4.z * ENV[i*4+2], sy2,     fy4.w * ENV[i*4+3] * sy3)));
    }

    float s1 = __sinf((float)lane * PI_INV);
    float c1 = __cosf((float)lane * PI_INV);
    const float stepA = 32.0f * PI_INV;
    const float sd = __sinf(stepA), cd = __cosf(stepA);

    const float fy = (float)y;
    const float HIG = __uint_as_float(0x43FF7FFFu);     // 510.99997
    // window clamps: inactive unless |dy| >= 1 (impossible, ~8 sigma)
    const float LOY = (y0 > 0) ? (float)(y0 - 1) : 0.0f;
    const float HIY = fminf(HIG, (float)(y0 + TILE_Y) - 0.001f);
    const float ybase = (float)(y0 - 1);

    // warp w taps local rows [w, w+2]; rows <= 10 are covered by group A
    mbar_wait(mbA);
    if (warp >= SPLIT_L - 2) mbar_wait(mbB);

    float* orow = out + (size_t)(b * C_) * (N_ * N_) + y * N_;

#pragma unroll 4
    for (int it = 0; it < 16; it++) {
        const int xi = it * 32 + lane;

        const float s2 = 2.0f * s1 * c1;
        const float c2 = fmaf(2.0f * c1, c1, -1.0f);
        const float s3 = fmaf(s1, c2, c1 * s2);
        const float s4 = 2.0f * s2 * c2;

        const float u = fmaf(gu[0], s1, fmaf(gu[1], s2, fmaf(gu[2], s3, gu[3] * s4)));
        const float v = fmaf(gv[0], s1, fmaf(gv[1], s2, fmaf(gv[2], s3, gv[3] * s4)));

        const float xn = fminf(fmaxf((float)xi - scale * u, 0.0f), HIG);
        const float yn = fminf(fmaxf(fy        - scale * v, LOY), HIY);

        const float xff = floorf(xn);
        const float yff = floorf(yn);
        const int   xf  = (int)xff;
        const float xv  = xn - xff;
        const float yv  = yn - yff;
        const int   r   = (int)(yff - ybase);           // local halo row

        const float w00 = (1.0f - yv) * (1.0f - xv);
        const float w01 = (1.0f - yv) * xv;
        const float w10 = yv * (1.0f - xv);
        const float w11 = yv * xv;

        const float* base = S + r * N_ + xf;            // taps: imm offsets

        float t[12];
#pragma unroll
        for (int c = 0; c < C_; c++) {
            const int off = c * CH_F;
            t[c*4+0] = base[off];
            t[c*4+1] = base[off + 1];
            t[c*4+2] = base[off + N_];
            t[c*4+3] = base[off + N_ + 1];
        }

        const float ns = fmaf(s1, cd,  c1 * sd);
        const float nc = fmaf(c1, cd, -s1 * sd);
        s1 = ns; c1 = nc;

#pragma unroll
        for (int c = 0; c < C_; c++) {
            float val = fmaf(w00, t[c*4+0], fmaf(w01, t[c*4+1],
                        fmaf(w10, t[c*4+2],      w11 * t[c*4+3])));
            __stcs(&orow[c * (N_ * N_) + xi], val);
        }
    }
}

extern "C" void kernel_launch(void* const* d_in, const int* in_sizes, int n_in,
                              void* d_out, int out_size) {
    const float* x  = (const float*)d_in[0];
    const float* Fx = (const float*)d_in[1];
    const float* Fy = (const float*)d_in[2];
    float* out = (float*)d_out;

    const double n_d  = (double)N_;
    const double typ  = n_d * sqrt(M_PI * log(4.0)) / 2.0;
    const double T    = 0.01;
    const float scale = (float)(sqrt(T / (typ * typ)) * n_d);

    cudaFuncSetAttribute(diffeo_kernel,
                         cudaFuncAttributeMaxDynamicSharedMemorySize, SMEM_BYTES);

    dim3 block(512);
    dim3 grid(N_ / TILE_Y, B_);
    diffeo_kernel<<<grid, block, SMEM_BYTES>>>(x, Fx, Fy, out, scale);
}

// round 13
// speedup vs baseline: 1.1424x; 1.0468x over previous
#include <cuda_runtime.h>
#include <math.h>
#include <stdint.h>

#define B_ 64
#define C_ 3
#define N_ 512
#define TILE_Y 4
#define HALO (TILE_Y + 2)                  // 6 rows incl. halo
#define CH_F (HALO * N_)                   // floats per channel tile (3072)
#define SMEM_BYTES (C_ * CH_F * 4)         // 36864

__device__ __forceinline__ uint32_t smem_u32(const void* p) {
    uint32_t a;
    asm("{ .reg .u64 t; cvta.to.shared.u64 t, %1; cvt.u32.u64 %0, t; }"
        : "=r"(a) : "l"(p));
    return a;
}

__global__ void __launch_bounds__(256)
diffeo_kernel(const float* __restrict__ x,
              const float* __restrict__ Fx,
              const float* __restrict__ Fy,
              float* __restrict__ out,
              float scale) {
    extern __shared__ float S[];                       // [3][HALO][512]
    __shared__ __align__(8) unsigned long long mbar;

    // envelope e[i][j] = 1/sqrt((i+1)^2+(j+1)^2), zeroed where r >= 4.5
    constexpr float ENV[16] = {
        0.7071067812f, 0.4472135955f, 0.3162277660f, 0.2425356250f,
        0.4472135955f, 0.3535533906f, 0.2773500981f, 0.2236067977f,
        0.3162277660f, 0.2773500981f, 0.2357022604f, 0.0f,
        0.2425356250f, 0.2236067977f, 0.0f,          0.0f
    };

    const int tid   = threadIdx.x;
    const int b     = blockIdx.y;
    const int warp  = tid >> 5;
    const int lane  = tid & 31;
    const int y0    = blockIdx.x * TILE_Y;
    const int y     = y0 + (warp >> 1);                // two warps per output row
    const int xhalf = (warp & 1) * 256;                // column half

    const uint32_t mb = smem_u32(&mbar);

    if (tid == 0) {
        asm volatile("mbarrier.init.shared.b64 [%0], %1;" :: "r"(mb), "r"(1u) : "memory");
    }
    __syncthreads();

    if (tid == 0) {
        int gy0 = y0 - 1, lr0 = 0;
        if (gy0 < 0) { gy0 = 0; lr0 = 1; }
        int gy1 = y0 + TILE_Y;
        if (gy1 > N_ - 1) gy1 = N_ - 1;
        const unsigned rbytes = (unsigned)(gy1 - gy0 + 1) * N_ * 4u;

        asm volatile("mbarrier.arrive.expect_tx.shared.b64 _, [%0], %1;"
                     :: "r"(mb), "r"(rbytes * 3u) : "memory");
#pragma unroll
        for (int c = 0; c < C_; c++) {
            const float* src = x + ((size_t)(b * C_ + c) * N_ + gy0) * N_;
            const uint32_t dst = smem_u32(S + c * CH_F + lr0 * N_);
            asm volatile(
                "cp.async.bulk.shared::cta.global.mbarrier::complete_tx::bytes "
                "[%0], [%1], %2, [%3];"
                :: "r"(dst), "l"(src), "r"(rbytes), "r"(mb) : "memory");
        }
    }

    // ---- per-warp row coefficients (overlaps the bulk copies) ----
    const float PI_INV = (float)M_PI / (float)(N_ - 1);
    const float py = (float)y * PI_INV;
    const float sy0 = __sinf(py), sy1 = __sinf(py * 2.0f);
    const float sy2 = __sinf(py * 3.0f), sy3 = __sinf(py * 4.0f);

    float gu[4], gv[4];
#pragma unroll
    for (int i = 0; i < 4; i++) {
        float4 fx  = __ldg((const float4*)(Fx + b * 16 + i * 4));
        float4 fy4 = __ldg((const float4*)(Fy + b * 16 + i * 4));
        gu[i] = fmaf(fx.x * ENV[i*4+0], sy0, fmaf(fx.y * ENV[i*4+1], sy1,
                fmaf(fx.z * ENV[i*4+2], sy2,      fx.w * ENV[i*4+3] * sy3)));
        gv[i] = fmaf(fy4.x * ENV[i*4+0], sy0, fmaf(fy4.y * ENV[i*4+1], sy1,
                fmaf(fy4.z * ENV[i*4+2], sy2,     fy4.w * ENV[i*4+3] * sy3)));
    }

    float s1 = __sinf((float)(xhalf + lane) * PI_INV);
    float c1 = __cosf((float)(xhalf + lane) * PI_INV);
    const float stepA = 32.0f * PI_INV;
    const float sd = __sinf(stepA), cd = __cosf(stepA);

    const float fy = (float)y;
    const float HIX = __uint_as_float(0x43FF7FFFu);                 // 510.99997
    // y-window clamp: inactive unless |dy| >= 1 (impossible; ~8 sigma)
    const float LOY = (y0 > 0) ? (float)(y0 - 1) : 0.0f;
    const float HIY = fminf(HIX, (float)(y0 + TILE_Y) - 0.001f);
    const float ybase = (float)(y0 - 1);

    // ---- wait for the tile (acquire orders subsequent ld.shared) ----
    {
        uint32_t done;
        asm volatile(
            "{\n .reg .pred p;\n"
            " mbarrier.try_wait.parity.acquire.cta.shared::cta.b64 p, [%1], %2;\n"
            " selp.b32 %0, 1, 0, p;\n}"
            : "=r"(done) : "r"(mb), "r"(0u) : "memory");
        while (!done) {
            asm volatile(
                "{\n .reg .pred p;\n"
                " mbarrier.try_wait.parity.acquire.cta.shared::cta.b64 p, [%1], %2, 0x989680;\n"
                " selp.b32 %0, 1, 0, p;\n}"
                : "=r"(done) : "r"(mb), "r"(0u) : "memory");
        }
    }

    float* orow = out + (size_t)(b * C_) * (N_ * N_) + y * N_;

#pragma unroll
    for (int it = 0; it < 8; it++) {
        const int xi = xhalf + it * 32 + lane;

        const float s2 = 2.0f * s1 * c1;
        const float c2 = fmaf(2.0f * c1, c1, -1.0f);
        const float s3 = fmaf(s1, c2, c1 * s2);
        const float s4 = 2.0f * s2 * c2;

        const float u = fmaf(gu[0], s1, fmaf(gu[1], s2, fmaf(gu[2], s3, gu[3] * s4)));
        const float v = fmaf(gv[0], s1, fmaf(gv[1], s2, fmaf(gv[2], s3, gv[3] * s4)));

        const float xn = fminf(fmaxf((float)xi - scale * u, 0.0f), HIX);
        const float yn = fminf(fmaxf(fy        - scale * v, LOY), HIY);

        const float xff = floorf(xn);
        const float yff = floorf(yn);
        const int   xf  = (int)xff;
        const float xv  = xn - xff;
        const float yv  = yn - yff;
        const int   r   = (int)(yff - ybase);          // local halo row 0..5

        const float w00 = (1.0f - yv) * (1.0f - xv);
        const float w01 = (1.0f - yv) * xv;
        const float w10 = yv * (1.0f - xv);
        const float w11 = yv * xv;

        const float* base = S + r * N_ + xf;           // taps: imm offsets

        float t[12];
#pragma unroll
        for (int c = 0; c < C_; c++) {
            const int off = c * CH_F;
            t[c*4+0] = base[off];
            t[c*4+1] = base[off + 1];
            t[c*4+2] = base[off + N_];
            t[c*4+3] = base[off + N_ + 1];
        }

        const float ns = fmaf(s1, cd,  c1 * sd);
        const float nc = fmaf(c1, cd, -s1 * sd);
        s1 = ns; c1 = nc;

#pragma unroll
        for (int c = 0; c < C_; c++) {
            float val = fmaf(w00, t[c*4+0], fmaf(w01, t[c*4+1],
                        fmaf(w10, t[c*4+2],      w11 * t[c*4+3])));
            __stcs(&orow[c * (N_ * N_) + xi], val);
        }
    }
}

extern "C" void kernel_launch(void* const* d_in, const int* in_sizes, int n_in,
                              void* d_out, int out_size) {
    const float* x  = (const float*)d_in[0];
    const float* Fx = (const float*)d_in[1];
    const float* Fy = (const float*)d_in[2];
    float* out = (float*)d_out;

    const double n_d  = (double)N_;
    const double typ  = n_d * sqrt(M_PI * log(4.0)) / 2.0;
    const double T    = 0.01;
    const float scale = (float)(sqrt(T / (typ * typ)) * n_d);

    cudaFuncSetAttribute(diffeo_kernel,
                         cudaFuncAttributeMaxDynamicSharedMemorySize, SMEM_BYTES);

    dim3 block(256);
    dim3 grid(N_ / TILE_Y, B_);
    diffeo_kernel<<<grid, block, SMEM_BYTES>>>(x, Fx, Fy, out, scale);
}